// round 7
// baseline (speedup 1.0000x reference)
#include <cuda_runtime.h>
#include <mma.h>
#include <cstdint>

// ============================================================================
// MyLinear: out[b,n,t,e] = sum_d x[b,n,t,d] * W[n,d,e] + bias[n,e]
// B=16, N=512, T=128, D_IN=64, D_OUT=64.
// wmma m16n16k8 tf32 (HMMA.TF32) — tcgen05 unavailable at compute_103.
// R7 (= R3 resubmit; four infra timeouts): occupancy push. 64-row x tiles,
// 16x32 warp tiles, 59.9KB smem, __launch_bounds__(256,3) -> 3 CTAs/SM.
// ============================================================================

using namespace nvcuda;

#define B_DIM   16
#define N_DIM   512
#define T_DIM   128
#define DIN     64
#define DOUT    64

#define B_PER_CTA 4          // grid.y = 4
#define ITERS     (B_PER_CTA * 2)   // (b, t-half) pairs

#define PAD     72           // row stride in floats (8-bank phase alignment)

// SMEM layout (floats)
#define SM_X0     0                    // x tile buf 0: 64 * PAD
#define SM_X1     (64 * PAD)           // x tile buf 1
#define SM_W      (2 * 64 * PAD)       // W tile: 64 * PAD
#define SM_BT     (3 * 64 * PAD)       // bias tile: 16 * PAD
#define SM_FLOATS (SM_BT + 16 * PAD)
#define SM_BYTES  (SM_FLOATS * 4)      // 59,904 B -> 3 CTAs/SM

static __device__ __forceinline__ uint32_t smem_u32(const void* p) {
    uint32_t a;
    asm("{ .reg .u64 t; cvta.to.shared.u64 t, %1; cvt.u32.u64 %0, t; }" : "=r"(a) : "l"(p));
    return a;
}

static __device__ __forceinline__ float f32_round_tf32(float f) {
    uint32_t u;
    asm("cvt.rna.tf32.f32 %0, %1;" : "=r"(u) : "f"(f));
    return __uint_as_float(u);
}

// cp.async one 64x64 f32 x tile into padded SMEM rows (stride PAD floats).
// 1024 16B chunks, 256 threads x 4.
static __device__ __forceinline__ void load_x_tile(uint32_t smem_tile_addr, const float* gx, int tid) {
#pragma unroll
    for (int j = 0; j < 4; j++) {
        int chunk = tid + j * 256;
        int r  = chunk >> 4;                 // row 0..63
        int kk = chunk & 15;                 // 16B unit within 64-float row
        uint32_t dst = smem_tile_addr + (uint32_t)(r * PAD + kk * 4) * 4u;
        asm volatile("cp.async.cg.shared.global [%0], [%1], 16;"
                     :: "r"(dst), "l"(gx + r * DIN + kk * 4));
    }
    asm volatile("cp.async.commit_group;" ::: "memory");
}

__global__ void __launch_bounds__(256, 3) mylinear_wmma_kernel(
    const float* __restrict__ x,
    const float* __restrict__ W,
    const float* __restrict__ bias,
    float* __restrict__ out
) {
    extern __shared__ float smem[];
    const uint32_t smem_base = smem_u32(smem);
    const int tid = threadIdx.x;
    const int wid = tid >> 5;
    const int n   = blockIdx.x;
    const int b0  = blockIdx.y * B_PER_CTA;

    // warp grid over 64x64 tile: 4 (M) x 2 (N); each warp 16 rows x 32 cols
    const int mw = wid >> 1;         // 0..3  -> row offset mw*16
    const int nw = wid & 1;          // 0..1  -> col offset nw*32

    // --- start streaming first x tile ASAP ---
    const float* x_base = x + ((size_t)(b0 * N_DIM + n)) * (T_DIM * DIN);
    load_x_tile(smem_base + SM_X0 * 4u, x_base, tid);

    // --- W[n] -> SMEM, rounded to tf32 (rna); layout [d][e] row-major, ldm=PAD ---
    const float* Wn = W + (size_t)n * (DIN * DOUT);
#pragma unroll
    for (int idx = tid; idx < DIN * DOUT; idx += 256) {
        int d = idx >> 6;
        int e = idx & 63;
        smem[SM_W + d * PAD + e] = f32_round_tf32(Wn[idx]);
    }

    // --- bias tile: 16 replicated rows of bias[n,:] ---
#pragma unroll
    for (int idx = tid; idx < 16 * DOUT; idx += 256) {
        int r = idx >> 6;
        int e = idx & 63;
        smem[SM_BT + r * PAD + e] = bias[n * DOUT + e];
    }
    __syncthreads();

#pragma unroll 1
    for (int i = 0; i < ITERS; i++) {
        const int b  = b0 + (i >> 1);
        const int th = i & 1;                 // T half: rows [th*64, th*64+64)

        // issue next tile into the other buffer, then wait for current
        if (i + 1 < ITERS) {
            const int bn  = b0 + ((i + 1) >> 1);
            const int thn = (i + 1) & 1;
            const float* x_next = x + (((size_t)(bn * N_DIM + n)) * T_DIM + thn * 64) * DIN;
            load_x_tile(smem_base + (((i + 1) & 1) ? SM_X1 : SM_X0) * 4u, x_next, tid);
            asm volatile("cp.async.wait_group 1;" ::: "memory");
        } else {
            asm volatile("cp.async.wait_group 0;" ::: "memory");
        }
        __syncthreads();

        const float* xbuf = smem + ((i & 1) ? SM_X1 : SM_X0);

        // --- accumulators initialized from bias tile (free bias add) ---
        wmma::fragment<wmma::accumulator, 16, 16, 8, float> acc[2];
#pragma unroll
        for (int ni = 0; ni < 2; ni++)
            wmma::load_matrix_sync(acc[ni],
                                   smem + SM_BT + (nw * 32 + ni * 16),
                                   PAD, wmma::mem_row_major);

        // --- K loop: 8 steps of k=8 ---
#pragma unroll
        for (int k = 0; k < 8; k++) {
            wmma::fragment<wmma::matrix_a, 16, 16, 8, wmma::precision::tf32, wmma::row_major> afrag;
            wmma::fragment<wmma::matrix_b, 16, 16, 8, wmma::precision::tf32, wmma::row_major> bfrag[2];
            wmma::load_matrix_sync(afrag, xbuf + (mw * 16) * PAD + k * 8, PAD);
#pragma unroll
            for (int ni = 0; ni < 2; ni++)
                wmma::load_matrix_sync(bfrag[ni],
                                       smem + SM_W + (k * 8) * PAD + (nw * 32 + ni * 16),
                                       PAD);
#pragma unroll
            for (int ni = 0; ni < 2; ni++)
                wmma::mma_sync(acc[ni], afrag, bfrag[ni], acc[ni]);
        }

        // --- store directly to global (row-major, ldm=64) ---
        float* obase = out + (((size_t)(b * N_DIM + n)) * T_DIM + th * 64 + mw * 16) * DOUT;
#pragma unroll
        for (int ni = 0; ni < 2; ni++)
            wmma::store_matrix_sync(obase + nw * 32 + ni * 16,
                                    acc[ni], DOUT, wmma::mem_row_major);

        __syncthreads();   // all warps done reading xbuf before refill
    }
}

extern "C" void kernel_launch(void* const* d_in, const int* in_sizes, int n_in,
                              void* d_out, int out_size) {
    const float* x    = (const float*)d_in[0];
    const float* W    = (const float*)d_in[1];
    const float* bias = (const float*)d_in[2];
    float* out        = (float*)d_out;

    cudaFuncSetAttribute(mylinear_wmma_kernel,
                         cudaFuncAttributeMaxDynamicSharedMemorySize, SM_BYTES);

    dim3 grid(N_DIM, B_DIM / B_PER_CTA);   // 512 x 4 = 2048 CTAs
    mylinear_wmma_kernel<<<grid, 256, SM_BYTES>>>(x, W, bias, out);
}

// round 12
// speedup vs baseline: 1.0829x; 1.0829x over previous
#include <cuda_runtime.h>
#include <mma.h>
#include <cstdint>

// ============================================================================
// MyLinear: out[b,n,t,e] = sum_d x[b,n,t,d] * W[n,d,e] + bias[n,e]
// B=16, N=512, T=128, D_IN=64, D_OUT=64.
// wmma m16n16k8 tf32 (HMMA.TF32) — tcgen05 unavailable at compute_103.
// R12 (= R8 resubmit; repeated infra timeouts): 128-row tiles @ occ 2, with
// the iteration-invariant W b-fragments HOISTED into registers (16 frags,
// 64 regs), halving per-iteration fragment LDS. Bias via accumulator init.
// ============================================================================

using namespace nvcuda;

#define B_DIM   16
#define N_DIM   512
#define T_DIM   128
#define DIN     64
#define DOUT    64
#define ITERS   8            // b's per CTA (grid.y = 2)

#define PAD     72           // row stride in floats

// SMEM layout (floats)
#define SM_X0     0                        // x tile buf 0: 128 * PAD
#define SM_X1     (128 * PAD)              // x tile buf 1
#define SM_W      (2 * 128 * PAD)          // W tile: 64 * PAD
#define SM_BT     (2 * 128 * PAD + 64*PAD) // bias tile: 16 * PAD
#define SM_FLOATS (SM_BT + 16 * PAD)
#define SM_BYTES  (SM_FLOATS * 4)          // 96,768 B -> 2 CTAs/SM

static __device__ __forceinline__ uint32_t smem_u32(const void* p) {
    uint32_t a;
    asm("{ .reg .u64 t; cvta.to.shared.u64 t, %1; cvt.u32.u64 %0, t; }" : "=r"(a) : "l"(p));
    return a;
}

static __device__ __forceinline__ float f32_round_tf32(float f) {
    uint32_t u;
    asm("cvt.rna.tf32.f32 %0, %1;" : "=r"(u) : "f"(f));
    return __uint_as_float(u);
}

// cp.async one 128x64 f32 x tile into padded SMEM rows (stride PAD floats).
// 2048 16B chunks, 256 threads x 8.
static __device__ __forceinline__ void load_x_tile(uint32_t smem_tile_addr, const float* gx, int tid) {
#pragma unroll
    for (int j = 0; j < 8; j++) {
        int chunk = tid + j * 256;
        int r  = chunk >> 4;                 // row 0..127
        int kk = chunk & 15;                 // 16B unit within 64-float row
        uint32_t dst = smem_tile_addr + (uint32_t)(r * PAD + kk * 4) * 4u;
        asm volatile("cp.async.cg.shared.global [%0], [%1], 16;"
                     :: "r"(dst), "l"(gx + r * DIN + kk * 4));
    }
    asm volatile("cp.async.commit_group;" ::: "memory");
}

__global__ void __launch_bounds__(256, 2) mylinear_wmma_kernel(
    const float* __restrict__ x,
    const float* __restrict__ W,
    const float* __restrict__ bias,
    float* __restrict__ out
) {
    extern __shared__ float smem[];
    const uint32_t smem_base = smem_u32(smem);
    const int tid = threadIdx.x;
    const int wid = tid >> 5;
    const int n   = blockIdx.x;
    const int b0  = blockIdx.y * ITERS;

    // warp grid over 128x64 tile: 4 (M) x 2 (N); each warp 32 rows x 32 cols
    const int mw = wid >> 1;         // 0..3  -> row offset mw*32
    const int nw = wid & 1;          // 0..1  -> col offset nw*32

    // --- start streaming first x tile ASAP ---
    const float* x_base = x + ((size_t)(b0 * N_DIM + n)) * (T_DIM * DIN);
    load_x_tile(smem_base + SM_X0 * 4u, x_base, tid);

    // --- W[n] -> SMEM, rounded to tf32 (rna); layout [d][e] row-major, ldm=PAD ---
    const float* Wn = W + (size_t)n * (DIN * DOUT);
#pragma unroll
    for (int idx = tid; idx < DIN * DOUT; idx += 256) {
        int d = idx >> 6;
        int e = idx & 63;
        smem[SM_W + d * PAD + e] = f32_round_tf32(Wn[idx]);
    }

    // --- bias tile: 16 replicated rows of bias[n,:] ---
#pragma unroll
    for (int idx = tid; idx < 16 * DOUT; idx += 256) {
        int r = idx >> 6;
        int e = idx & 63;
        smem[SM_BT + r * PAD + e] = bias[n * DOUT + e];
    }
    __syncthreads();

    // --- HOIST: W b-fragments for this warp's 32-col slice, all 8 k-steps.
    //     Iteration-invariant; 16 frags x 4 regs = 64 registers. ---
    wmma::fragment<wmma::matrix_b, 16, 16, 8, wmma::precision::tf32, wmma::row_major> bfrag[8][2];
#pragma unroll
    for (int k = 0; k < 8; k++)
#pragma unroll
        for (int ni = 0; ni < 2; ni++)
            wmma::load_matrix_sync(bfrag[k][ni],
                                   smem + SM_W + (k * 8) * PAD + (nw * 32 + ni * 16),
                                   PAD);

#pragma unroll 1
    for (int i = 0; i < ITERS; i++) {
        const int b = b0 + i;

        // issue next tile into the other buffer, then wait for current
        if (i + 1 < ITERS) {
            const float* x_next = x + ((size_t)((b + 1) * N_DIM + n)) * (T_DIM * DIN);
            load_x_tile(smem_base + (((i + 1) & 1) ? SM_X1 : SM_X0) * 4u, x_next, tid);
            asm volatile("cp.async.wait_group 1;" ::: "memory");
        } else {
            asm volatile("cp.async.wait_group 0;" ::: "memory");
        }
        __syncthreads();

        const float* xbuf = smem + ((i & 1) ? SM_X1 : SM_X0);

        // --- accumulators initialized from bias tile (free bias add) ---
        wmma::fragment<wmma::accumulator, 16, 16, 8, float> acc[2][2];
#pragma unroll
        for (int mi = 0; mi < 2; mi++)
#pragma unroll
            for (int ni = 0; ni < 2; ni++)
                wmma::load_matrix_sync(acc[mi][ni],
                                       smem + SM_BT + (nw * 32 + ni * 16),
                                       PAD, wmma::mem_row_major);

        // --- K loop: only A fragments come from smem now ---
#pragma unroll
        for (int k = 0; k < 8; k++) {
            wmma::fragment<wmma::matrix_a, 16, 16, 8, wmma::precision::tf32, wmma::row_major> afrag[2];
#pragma unroll
            for (int mi = 0; mi < 2; mi++)
                wmma::load_matrix_sync(afrag[mi],
                                       xbuf + (mw * 32 + mi * 16) * PAD + k * 8,
                                       PAD);
#pragma unroll
            for (int mi = 0; mi < 2; mi++)
#pragma unroll
                for (int ni = 0; ni < 2; ni++)
                    wmma::mma_sync(acc[mi][ni], afrag[mi], bfrag[k][ni], acc[mi][ni]);
        }

        // --- store directly to global (row-major, ldm=64) ---
        float* obase = out + (((size_t)(b * N_DIM + n)) * T_DIM + mw * 32) * DOUT;
#pragma unroll
        for (int mi = 0; mi < 2; mi++)
#pragma unroll
            for (int ni = 0; ni < 2; ni++)
                wmma::store_matrix_sync(obase + mi * 16 * DOUT + nw * 32 + ni * 16,
                                        acc[mi][ni], DOUT, wmma::mem_row_major);

        __syncthreads();   // all warps done reading xbuf before refill
    }
}

extern "C" void kernel_launch(void* const* d_in, const int* in_sizes, int n_in,
                              void* d_out, int out_size) {
    const float* x    = (const float*)d_in[0];
    const float* W    = (const float*)d_in[1];
    const float* bias = (const float*)d_in[2];
    float* out        = (float*)d_out;

    cudaFuncSetAttribute(mylinear_wmma_kernel,
                         cudaFuncAttributeMaxDynamicSharedMemorySize, SM_BYTES);

    dim3 grid(N_DIM, B_DIM / ITERS);   // 512 x 2 = 1024 CTAs
    mylinear_wmma_kernel<<<grid, 256, SM_BYTES>>>(x, W, bias, out);
}